// round 2
// baseline (speedup 1.0000x reference)
#include <cuda_runtime.h>

// Problem constants
#define B_  1024
#define N_  128     // nodes == K (reduction dim)
#define H_  128
#define D_  8
#define HD_ (H_ * D_)            // 1024
#define BT  128                  // batch rows per block
#define CN  64                   // columns per weight chunk
#define NCHUNK_G (HD_ / CN)      // 16
#define NCHUNK_F (H_ / CN)       // 2
#define NCHUNK   (NCHUNK_G + NCHUNK_F)  // 18
#define XS_STRIDE 132            // padded row stride for transposed x tile
#define THREADS 256
#define SMEM_BYTES ((N_ * XS_STRIDE + N_ * CN) * 4)   // 67584 + 32768 = 100352

// ---- packed f32x2 helpers (sm_103a FFMA2 path) ----
__device__ __forceinline__ unsigned long long pack2(float v) {
    unsigned long long r;
    asm("mov.b64 %0, {%1, %1};" : "=l"(r) : "r"(__float_as_uint(v)));
    return r;
}
__device__ __forceinline__ void fma2(unsigned long long& d,
                                     unsigned long long a,
                                     unsigned long long b) {
    asm("fma.rn.f32x2 %0, %1, %2, %0;" : "+l"(d) : "l"(a), "l"(b));
}
__device__ __forceinline__ float2 unpack2(unsigned long long v) {
    unsigned lo, hi;
    asm("mov.b64 {%0, %1}, %2;" : "=r"(lo), "=r"(hi) : "l"(v));
    float2 f;
    f.x = __uint_as_float(lo);
    f.y = __uint_as_float(hi);
    return f;
}

__device__ __forceinline__ float elu1(float x) {
    return x > 0.0f ? x : (__expf(x) - 1.0f);
}

__global__ __launch_bounds__(THREADS, 2)
void sde_fused_kernel(const float* __restrict__ x,
                      const float* __restrict__ fw,   // [N,N,H]
                      const float* __restrict__ gw,   // [N,N,H,D]
                      const float* __restrict__ Wf,   // [N,H]
                      const float* __restrict__ bf,   // [N]
                      const float* __restrict__ Wg,   // [N,H]
                      const float* __restrict__ bg,   // [N]
                      float* __restrict__ fout,       // [B,N]
                      float* __restrict__ gout)       // [B,N,D]
{
    extern __shared__ float smem[];
    float* x_s = smem;                       // [k=128][row=128], stride 132
    float* W_s = smem + N_ * XS_STRIDE;      // [k=128][64]

    const int tid = threadIdx.x;
    const int i   = blockIdx.y;              // node
    const int b0  = blockIdx.x * BT;         // batch row base
    const int cx  = tid & 7;                 // column group (8 cols each)
    const int rx  = tid >> 3;                // row group (4 rows each)
    const int rx4 = rx * 4;
    const int cx8 = cx * 8;

    // Load x tile [BT x N] transposed into x_s[k][row]
    for (int idx = tid; idx < BT * N_; idx += THREADS) {
        int r = idx >> 7;
        int n = idx & 127;
        x_s[n * XS_STRIDE + r] = x[(size_t)(b0 + r) * N_ + n];
    }

    float accg[4][8];
    float accf[4];
#pragma unroll
    for (int r = 0; r < 4; ++r) {
        accf[r] = 0.0f;
#pragma unroll
        for (int d = 0; d < 8; ++d) accg[r][d] = 0.0f;
    }

    for (int chunk = 0; chunk < NCHUNK; ++chunk) {
        __syncthreads();   // previous chunk's compute done before overwrite

        // Load weight chunk [128 x 64]
        const float* src;
        int stride;
        if (chunk < NCHUNK_G) {
            src = gw + (size_t)i * N_ * HD_ + chunk * CN;
            stride = HD_;
        } else {
            src = fw + (size_t)i * N_ * H_ + (chunk - NCHUNK_G) * CN;
            stride = H_;
        }
        for (int idx = tid; idx < N_ * (CN / 4); idx += THREADS) {
            int n  = idx >> 4;
            int c4 = idx & 15;
            float4 v = *(const float4*)(src + (size_t)n * stride + c4 * 4);
            *(float4*)(W_s + n * CN + c4 * 4) = v;
        }
        __syncthreads();

        // 128x64 GEMM tile over K=128, packed f32x2 accumulators
        unsigned long long acc[16];
#pragma unroll
        for (int t = 0; t < 16; ++t) acc[t] = 0ull;

#pragma unroll 4
        for (int k = 0; k < N_; ++k) {
            float4 av = *(const float4*)(x_s + k * XS_STRIDE + rx4);
            const ulonglong2* wr = (const ulonglong2*)(W_s + k * CN + cx8);
            ulonglong2 p01 = wr[0];
            ulonglong2 p23 = wr[1];
            unsigned long long a0 = pack2(av.x);
            unsigned long long a1 = pack2(av.y);
            unsigned long long a2 = pack2(av.z);
            unsigned long long a3 = pack2(av.w);
            fma2(acc[0],  a0, p01.x); fma2(acc[1],  a0, p01.y);
            fma2(acc[2],  a0, p23.x); fma2(acc[3],  a0, p23.y);
            fma2(acc[4],  a1, p01.x); fma2(acc[5],  a1, p01.y);
            fma2(acc[6],  a1, p23.x); fma2(acc[7],  a1, p23.y);
            fma2(acc[8],  a2, p01.x); fma2(acc[9],  a2, p01.y);
            fma2(acc[10], a2, p23.x); fma2(acc[11], a2, p23.y);
            fma2(acc[12], a3, p01.x); fma2(acc[13], a3, p01.y);
            fma2(acc[14], a3, p23.x); fma2(acc[15], a3, p23.y);
        }

        // Epilogue: elu + weighted accumulate (registers only)
        if (chunk < NCHUNK_G) {
            // this thread's 8 columns are the 8 diffusion channels of h:
            const float w = Wg[i * H_ + chunk * 8 + cx];
#pragma unroll
            for (int r = 0; r < 4; ++r) {
#pragma unroll
                for (int p = 0; p < 4; ++p) {
                    float2 c = unpack2(acc[r * 4 + p]);
                    accg[r][2 * p]     += w * elu1(c.x);
                    accg[r][2 * p + 1] += w * elu1(c.y);
                }
            }
        } else {
            const int hb = (chunk - NCHUNK_G) * CN + cx8;
            float wf[8];
#pragma unroll
            for (int j = 0; j < 8; ++j) wf[j] = Wf[i * H_ + hb + j];
#pragma unroll
            for (int r = 0; r < 4; ++r) {
#pragma unroll
                for (int p = 0; p < 4; ++p) {
                    float2 c = unpack2(acc[r * 4 + p]);
                    accf[r] += wf[2 * p] * elu1(c.x) + wf[2 * p + 1] * elu1(c.y);
                }
            }
        }
    }

    // Reduce across the 8 column-group lanes (cx) within each octet
#pragma unroll
    for (int r = 0; r < 4; ++r) {
#pragma unroll
        for (int d = 0; d < 8; ++d) {
            float v = accg[r][d];
            v += __shfl_xor_sync(0xffffffffu, v, 1);
            v += __shfl_xor_sync(0xffffffffu, v, 2);
            v += __shfl_xor_sync(0xffffffffu, v, 4);
            accg[r][d] = v;
        }
        float vf = accf[r];
        vf += __shfl_xor_sync(0xffffffffu, vf, 1);
        vf += __shfl_xor_sync(0xffffffffu, vf, 2);
        vf += __shfl_xor_sync(0xffffffffu, vf, 4);
        accf[r] = vf;
    }

    if (cx == 0) {
        const float bgi = bg[i];
        const float bfi = bf[i];
#pragma unroll
        for (int r = 0; r < 4; ++r) {
            const int row = b0 + rx4 + r;
            fout[(size_t)row * N_ + i] = accf[r] + bfi;
            float* gp = gout + ((size_t)row * N_ + i) * D_;
#pragma unroll
            for (int d = 0; d < 8; ++d) gp[d] = accg[r][d] + bgi;
        }
    }
}

extern "C" void kernel_launch(void* const* d_in, const int* in_sizes, int n_in,
                              void* d_out, int out_size) {
    (void)in_sizes; (void)n_in; (void)out_size;
    const float* x  = (const float*)d_in[0];
    const float* fw = (const float*)d_in[1];
    const float* gw = (const float*)d_in[2];
    const float* Wf = (const float*)d_in[3];
    const float* bf = (const float*)d_in[4];
    const float* Wg = (const float*)d_in[5];
    const float* bg = (const float*)d_in[6];

    float* out  = (float*)d_out;
    float* fout = out;                       // [B,N]
    float* gout = out + (size_t)B_ * N_;     // [B,N,D]

    cudaFuncSetAttribute(sde_fused_kernel,
                         cudaFuncAttributeMaxDynamicSharedMemorySize, SMEM_BYTES);

    dim3 grid(B_ / BT, N_);
    sde_fused_kernel<<<grid, THREADS, SMEM_BYTES>>>(x, fw, gw, Wf, bf, Wg, bg,
                                                    fout, gout);
}

// round 5
// speedup vs baseline: 1.6891x; 1.6891x over previous
#include <cuda_runtime.h>
#include <cuda_bf16.h>
#include <cstdint>

#define B_ 1024
#define N_ 128
#define H_ 128
#define D_ 8
#define NT 9   // 8 g col-tiles (128 cols) + 1 f tile

// Packed operands (prep kernels write, main reads)
// g_xa: [mtile 8][chunk 16][m 128][k16] bf16 pairs; chunks 0-7 = Xhi, 8-15 = Xlo
__device__ __align__(16) unsigned g_xa[8 * 16 * 128 * 8];          // 512KB
// g_pb: per (node,tile): [chunk 16][n 128][k16] bf16 pairs; chunks 0-7 Whi, 8-15 Wlo
__device__ __align__(16) unsigned g_pb[(size_t)N_ * NT * 16384];   // 75.5MB

// ---------------- helpers ----------------
__device__ __forceinline__ uint32_t smem_u32(const void* p) {
    uint32_t a;
    asm("{ .reg .u64 t; cvta.to.shared.u64 t, %1; cvt.u32.u64 %0, t; }" : "=r"(a) : "l"(p));
    return a;
}
__device__ __forceinline__ unsigned pack_bf16(float f0, float f1, bool lo) {
    __nv_bfloat16 h0 = __float2bfloat16_rn(f0), h1 = __float2bfloat16_rn(f1);
    if (lo) {
        h0 = __float2bfloat16_rn(f0 - __bfloat162float(h0));
        h1 = __float2bfloat16_rn(f1 - __bfloat162float(h1));
    }
    __nv_bfloat162 t = __halves2bfloat162(h0, h1);
    return *reinterpret_cast<unsigned*>(&t);
}
// MUFU-free ELU: exp(x)-1 via exp2 poly + exponent-field add
__device__ __forceinline__ float elu_fast(float x) {
    float t = fmaxf(x, -30.0f) * 1.4426950408889634f;
    int   ji = __float2int_rn(t);
    float f  = t - (float)ji;
    float p = 1.3333558146e-3f;
    p = fmaf(p, f, 9.6181291076e-3f);
    p = fmaf(p, f, 5.5504108664e-2f);
    p = fmaf(p, f, 2.4022650696e-1f);
    p = fmaf(p, f, 6.9314718056e-1f);
    p = fmaf(p, f, 1.0f);
    float r = __int_as_float(__float_as_int(p) + (ji << 23)) - 1.0f;
    return x > 0.0f ? x : r;
}

#define CP16(s, g) asm volatile("cp.async.cg.shared.global [%0], [%1], 16;" :: "r"(s), "l"(g))
#define CP_COMMIT() asm volatile("cp.async.commit_group;" ::: "memory")
#define CP_WAIT(n)  asm volatile("cp.async.wait_group %0;" :: "n"(n) : "memory")

#define LDM4(r0, r1, r2, r3, a) \
    asm volatile("ldmatrix.sync.aligned.m8n8.x4.shared.b16 {%0,%1,%2,%3}, [%4];" \
        : "=r"(r0), "=r"(r1), "=r"(r2), "=r"(r3) : "r"(a))

#define MMA16816(c, a, b) \
    asm volatile("mma.sync.aligned.m16n8k16.row.col.f32.bf16.bf16.f32 " \
        "{%0,%1,%2,%3}, {%4,%5,%6,%7}, {%8,%9}, {%0,%1,%2,%3};" \
        : "+f"((c)[0]), "+f"((c)[1]), "+f"((c)[2]), "+f"((c)[3]) \
        : "r"((a)[0]), "r"((a)[1]), "r"((a)[2]), "r"((a)[3]), "r"((b)[0]), "r"((b)[1]))

// ---------------- prep: x -> g_xa ----------------
__global__ void prep_x(const float* __restrict__ x) {
    int idx = blockIdx.x * blockDim.x + threadIdx.x;       // one u32 each
    if (idx >= 131072) return;
    int mt = idx >> 14;             // 16384 u32 per m-tile
    int c  = (idx >> 10) & 15;      // chunk 0..15
    int m  = (idx >> 3) & 127;
    int p  = idx & 7;
    int row = mt * 128 + m;
    int kb = (c & 7) * 16 + 2 * p;
    bool lo = c >= 8;
    g_xa[idx] = pack_bf16(x[row * 128 + kb], x[row * 128 + kb + 1], lo);
}

// ---------------- prep: weights -> g_pb ----------------
__global__ void prep_w(const float* __restrict__ fw, const float* __restrict__ gw) {
    extern __shared__ float s[];               // s[n*132 + k]
    const int t = blockIdx.x, i = blockIdx.y, tid = threadIdx.x;
    const float* src = (t < 8) ? (gw + (size_t)i * 131072 + t * 128)
                               : (fw + (size_t)i * 16384);
    const int stride = (t < 8) ? 1024 : 128;
    for (int idx = tid; idx < 128 * 128; idx += 256) {
        int k = idx >> 7, n = idx & 127;
        s[n * 132 + k] = src[(size_t)k * stride + n];
    }
    __syncthreads();
    unsigned* out = g_pb + (size_t)(i * NT + t) * 16384;
    for (int v = 0; v < 16; ++v) {
        int o = (v * 256 + tid) * 4;           // u32 index of uint4
        int c = o >> 10, n = (o >> 3) & 127, p0 = o & 7;
        int kb = (c & 7) * 16 + 2 * p0;
        bool lo = c >= 8;
        const float* sp = &s[n * 132 + kb];
        uint4 val;
        val.x = pack_bf16(sp[0], sp[1], lo);
        val.y = pack_bf16(sp[2], sp[3], lo);
        val.z = pack_bf16(sp[4], sp[5], lo);
        val.w = pack_bf16(sp[6], sp[7], lo);
        *reinterpret_cast<uint4*>(out + o) = val;
    }
}

// ---------------- main fused kernel ----------------
// smem: XA 64KB | B0 64KB | B1 64KB | Wg 512B | Wf 512B
#define SM_XA 0
#define SM_B0 65536
#define SM_WG 196608
#define SM_WF 197120
#define SM_TOT 197632

__global__ __launch_bounds__(128, 1)
void sde_main(const float* __restrict__ Wf, const float* __restrict__ bfv,
              const float* __restrict__ Wg, const float* __restrict__ bgv,
              float* __restrict__ fout, float* __restrict__ gout) {
    extern __shared__ char smem[];
    const uint32_t sb = smem_u32(smem);
    const int tid = threadIdx.x, l = tid & 31, wid = tid >> 5;
    const int i = blockIdx.y, b0 = blockIdx.x * 128;
    const int warp_m = (wid & 1) * 64;
    const int warp_n = (wid >> 1) * 64;
    float* Wg_s = (float*)(smem + SM_WG);
    float* Wf_s = (float*)(smem + SM_WF);

    // stage A (X hi/lo, 64KB) + B tile 0, one group
    const char* asrc = (const char*)g_xa + (size_t)blockIdx.x * 65536;
    const char* bsrc = (const char*)(g_pb + (size_t)(i * NT) * 16384);
    for (int j = 0; j < 32; ++j) {
        uint32_t off = (uint32_t)(j * 128 + tid) * 16;
        CP16(sb + SM_XA + off, asrc + off);
        CP16(sb + SM_B0 + off, bsrc + off);
    }
    CP_COMMIT();
    Wg_s[tid] = Wg[i * H_ + tid];
    Wf_s[tid] = Wf[i * H_ + tid];

    const uint32_t aoff = (uint32_t)((warp_m + (l & 15)) * 32 + (l >> 4) * 16);
    const uint32_t boff = (uint32_t)((warp_n + (l & 15)) * 32 + (l >> 4) * 16);

    float accg[8][2];
    float accf[8];
#pragma unroll
    for (int r = 0; r < 8; ++r) { accg[r][0] = 0.f; accg[r][1] = 0.f; accf[r] = 0.f; }

    for (int t = 0; t < NT; ++t) {
        if (t + 1 < NT) {   // prefetch next B tile into other buffer
            uint32_t dst = sb + SM_B0 + ((t + 1) & 1) * 65536;
            const char* src = bsrc + (size_t)(t + 1) * 65536;
            for (int j = 0; j < 32; ++j) {
                uint32_t off = (uint32_t)(j * 128 + tid) * 16;
                CP16(dst + off, src + off);
            }
            CP_COMMIT();
            CP_WAIT(1);
        } else {
            CP_WAIT(0);
        }
        __syncthreads();

        const uint32_t bbase = sb + SM_B0 + (t & 1) * 65536;
        float acc[8][4][4];
#pragma unroll
        for (int in = 0; in < 8; ++in)
#pragma unroll
            for (int im = 0; im < 4; ++im)
#pragma unroll
                for (int r = 0; r < 4; ++r) acc[in][im][r] = 0.f;

#pragma unroll
        for (int s = 0; s < 24; ++s) {
            const uint32_t ab = sb + SM_XA + (uint32_t)(((s < 16) ? s : s - 16) * 4096) + aoff;
            const uint32_t bb = bbase + (uint32_t)(((s < 8) ? s : s - 8) * 4096) + boff;
            uint32_t af[4][4], bfr[8][2];
#pragma unroll
            for (int im = 0; im < 4; ++im)
                LDM4(af[im][0], af[im][1], af[im][2], af[im][3], ab + im * 512);
#pragma unroll
            for (int pr = 0; pr < 4; ++pr)
                LDM4(bfr[2 * pr][0], bfr[2 * pr + 1][0],
                     bfr[2 * pr][1], bfr[2 * pr + 1][1], bb + pr * 512);
#pragma unroll
            for (int im = 0; im < 4; ++im)
#pragma unroll
                for (int in = 0; in < 8; ++in)
                    MMA16816(acc[in][im], af[im], bfr[in]);
        }

        // fused epilogue
        if (t < 8) {
            const int hb = t * 16 + (wid >> 1) * 8;
#pragma unroll
            for (int in = 0; in < 8; ++in) {
                const float w = Wg_s[hb + in];
#pragma unroll
                for (int im = 0; im < 4; ++im) {
                    accg[im * 2][0]     = fmaf(w, elu_fast(acc[in][im][0]), accg[im * 2][0]);
                    accg[im * 2][1]     = fmaf(w, elu_fast(acc[in][im][1]), accg[im * 2][1]);
                    accg[im * 2 + 1][0] = fmaf(w, elu_fast(acc[in][im][2]), accg[im * 2 + 1][0]);
                    accg[im * 2 + 1][1] = fmaf(w, elu_fast(acc[in][im][3]), accg[im * 2 + 1][1]);
                }
            }
        } else {
            const int cb = warp_n + 2 * (l & 3);
#pragma unroll
            for (int in = 0; in < 8; ++in) {
                const float w0 = Wf_s[cb + in * 8], w1 = Wf_s[cb + in * 8 + 1];
#pragma unroll
                for (int im = 0; im < 4; ++im) {
                    accf[im * 2]     += w0 * elu_fast(acc[in][im][0]) + w1 * elu_fast(acc[in][im][1]);
                    accf[im * 2 + 1] += w0 * elu_fast(acc[in][im][2]) + w1 * elu_fast(acc[in][im][3]);
                }
            }
        }
        __syncthreads();   // everyone done with buffers before overwrite / reuse
    }

    // cross-warp reduction: warps 2,3 (n=64..127) hand partials to warps 0,1
    float* red = (float*)smem;     // reuse XA region
    const int base = ((wid & 1) * 32 + l) * 24;
    if (wid >= 2) {
#pragma unroll
        for (int r = 0; r < 8; ++r) {
            red[base + r * 2]     = accg[r][0];
            red[base + r * 2 + 1] = accg[r][1];
            red[base + 16 + r]    = accf[r];
        }
    }
    __syncthreads();
    if (wid < 2) {
#pragma unroll
        for (int r = 0; r < 8; ++r) {
            accg[r][0] += red[base + r * 2];
            accg[r][1] += red[base + r * 2 + 1];
            accf[r]    += red[base + 16 + r];
        }
        const float bgi = bgv[i], bfi = bfv[i];
#pragma unroll
        for (int r = 0; r < 8; ++r) {
            const int row = b0 + warp_m + (r >> 1) * 16 + (r & 1) * 8 + (l >> 2);
            float2 v = make_float2(accg[r][0] + bgi, accg[r][1] + bgi);
            *reinterpret_cast<float2*>(gout + ((size_t)row * 128 + i) * 8 + 2 * (l & 3)) = v;
            float vf = accf[r];
            vf += __shfl_xor_sync(0xffffffffu, vf, 1);
            vf += __shfl_xor_sync(0xffffffffu, vf, 2);
            if ((l & 3) == 0) fout[(size_t)row * 128 + i] = vf + bfi;
        }
    }
}

// ---------------- launch ----------------
extern "C" void kernel_launch(void* const* d_in, const int* in_sizes, int n_in,
                              void* d_out, int out_size) {
    (void)in_sizes; (void)n_in; (void)out_size;
    const float* x  = (const float*)d_in[0];
    const float* fw = (const float*)d_in[1];
    const float* gw = (const float*)d_in[2];
    const float* Wf = (const float*)d_in[3];
    const float* bf = (const float*)d_in[4];
    const float* Wg = (const float*)d_in[5];
    const float* bg = (const float*)d_in[6];
    float* out  = (float*)d_out;
    float* fout = out;                      // [B,N]
    float* gout = out + (size_t)B_ * N_;    // [B,N,D]

    static bool attr_set = false;
    if (!attr_set) {
        cudaFuncSetAttribute(prep_w, cudaFuncAttributeMaxDynamicSharedMemorySize, 128 * 132 * 4);
        cudaFuncSetAttribute(sde_main, cudaFuncAttributeMaxDynamicSharedMemorySize, SM_TOT);
        attr_set = true;
    }

    prep_x<<<512, 256>>>(x);
    prep_w<<<dim3(NT, N_), 256, 128 * 132 * 4>>>(fw, gw);
    sde_main<<<dim3(8, N_), 128, SM_TOT>>>(Wf, bf, Wg, bg, fout, gout);
}